// round 9
// baseline (speedup 1.0000x reference)
#include <cuda_runtime.h>
#include <cstdint>

// SpottingLoss: greedy bipartite matching + YOLO-style loss.
// B=2048 batches, N=64 slots, F=19 features. One 64-thread CTA per batch.
// R8 = R7 + cp.async (LDGSTS) staging of both tiles into smem, overlapped
//      with the matching loop (no register scoreboard -> does not violate the
//      "minimal front-load" invariant). Epilogue becomes pure LDS.
// Matching core: phase-1 eliminated, pm-poison free-set, 8x8 tree argmax.

#define N_ 64
#define F_ 19
#define TILE_FLOATS (N_ * F_)            // 1216
#define TILE_CHUNKS (TILE_FLOATS / 4)    // 304 x 16B per tile
#define LAMBDA_COORD 5.0f
#define LAMBDA_NOOBJ 0.5f
#define FULLM 0xFFFFFFFFu

// Grid-reduction scratch. Zero-initialized at module load; the LAST block of
// every launch resets both, so each graph replay starts clean.
__device__ float    g_acc   = 0.0f;
__device__ unsigned g_count = 0u;

// Column-acceptance key: (value bits << 32) | ~row. Proposal values are > 0,
// so float bits are monotone; larger key = larger value, then lower row index
// — exactly the reference's argmax-over-rows tie-breaking.
__device__ __forceinline__ unsigned long long mk_key(float v, int row) {
    return ((unsigned long long)__float_as_uint(v) << 32) |
           (unsigned long long)(FULLM - (unsigned)row);
}

__device__ __forceinline__ void cp_async16(uint32_t smem_dst, const void* gsrc) {
    asm volatile("cp.async.cg.shared.global [%0], [%1], 16;"
                 :: "r"(smem_dst), "l"(gsrc) : "memory");
}

__global__ __launch_bounds__(N_) void spotting_loss_kernel(
    const float* __restrict__ y_true,
    const float* __restrict__ y_pred,
    float* __restrict__ out)
{
    // Full tiles, staged by cp.async during matching (row stride 19 is
    // coprime with 32 banks -> epilogue LDS is conflict-free).
    __shared__ __align__(16) float yt_s[TILE_FLOATS];
    __shared__ __align__(16) float yp_s[TILE_FLOATS];
    // pm[j] = y_pred[j][1] while column j is free; poisoned to 3.0f once
    // matched (v = 1-|x-3| < 0 never beats a free column's v > 0).
    // After matching, pm[j]==3.0f doubles as the "column taken" flag.
    __shared__ float pm[N_];
    __shared__ unsigned long long colkey[N_];
    __shared__ float red[2];

    const int b   = blockIdx.x;
    const int tid = threadIdx.x;

    const float* gt = y_true + (size_t)b * TILE_FLOATS;
    const float* gp = y_pred + (size_t)b * TILE_FLOATS;

    // Minimal register-scoreboard footprint: exactly 3 LDGs per thread.
    const float alpha = __ldg(gt + tid * F_ + 0);   // exactly 0.0f or 1.0f
    const float x     = __ldg(gt + tid * F_ + 1);
    pm[tid]     = __ldg(gp + tid * F_ + 1);

    // Fire-and-forget tile staging: 2*304 16B chunks over 64 threads.
    // LDGSTS has no register scoreboard; matching below hides the latency.
    {
        uint32_t yt_base = (uint32_t)__cvta_generic_to_shared(yt_s);
        uint32_t yp_base = (uint32_t)__cvta_generic_to_shared(yp_s);
        const char* gt_b = (const char*)gt;
        const char* gp_b = (const char*)gp;
#pragma unroll
        for (int it = 0; it < 2 * TILE_CHUNKS / N_ + 1; ++it) {   // 10 iters
            int idx = tid + it * N_;
            if (idx < TILE_CHUNKS)
                cp_async16(yt_base + idx * 16, gt_b + idx * 16);
            else if (idx < 2 * TILE_CHUNKS)
                cp_async16(yp_base + (idx - TILE_CHUNKS) * 16,
                           gp_b + (idx - TILE_CHUNKS) * 16);
        }
        asm volatile("cp.async.commit_group;" ::: "memory");
    }

    colkey[tid] = 0ull;           // init once; never reset (round invariant)
    __syncthreads();

    int  perm   = 0;
    bool active = (alpha > 0.5f);                   // only alpha=1 rows match

    // Invariant: every column proposed in a round is matched in that round,
    // so colkey entries are never reused and pm poison is the only free-set.
    for (;;) {
        if (__syncthreads_count(active) == 0) break;  // barrier A
        // (also orders last round's pm poison writes before this scan)

        int bj = 0;
        if (active) {
            // Two-level argmax over all 64 columns: 8 independent chunk
            // chains (ILP=8), then serial combine. Strict > keeps the
            // lowest index on ties in both levels = JAX argmax semantics.
            float cv[8]; int cj[8];
#pragma unroll
            for (int c = 0; c < 8; ++c) {
                float bv = -10.0f; int bi = c * 8;
#pragma unroll
                for (int k = 0; k < 8; ++k) {
                    int j = c * 8 + k;
                    float v = 1.0f - fabsf(x - pm[j]);
                    if (v > bv) { bv = v; bi = j; }
                }
                cv[c] = bv; cj[c] = bi;
            }
            float bv = cv[0]; bj = cj[0];
#pragma unroll
            for (int c = 1; c < 8; ++c)
                if (cv[c] > bv) { bv = cv[c]; bj = cj[c]; }

            atomicMax(&colkey[bj], mk_key(bv, tid));
        }
        __syncthreads();                              // barrier B

        if (active) {
            unsigned wr = FULLM - (unsigned)(colkey[bj] & 0xFFFFFFFFull);
            if (wr == (unsigned)tid) {                // column accepted us
                perm   = bj;
                active = false;
                pm[bj] = 3.0f;    // poison: single writer, ordered by barrier A
            }
        }
    }

    // Tiles must be resident before the epilogue; by now the LDGSTS queue has
    // had the whole matching loop to drain, so this wait is (usually) free.
    asm volatile("cp.async.wait_group 0;" ::: "memory");
    __syncthreads();   // pm poison flags + staged tiles visible to all

    float term = 0.0f;

    // alpha=1 row term: full YOLO loss vs permuted prediction row (all LDS).
    if (alpha > 0.5f) {
        const float* gtr = &yt_s[tid * F_];
        const float* ypr = &yp_s[perm * F_];
        const float d0 = 1.0f - ypr[0];
        const float dx = x - ypr[1];
        float s = 0.0f;
#pragma unroll
        for (int f = 2; f < F_; ++f) {
            float d = gtr[f] - ypr[f];
            s += d * d;
        }
        term += LAMBDA_COORD * dx * dx + d0 * d0 + s;
    }

    // alpha=0 contribution, per COLUMN: every column not taken in phase 0 is
    // assigned to exactly one alpha=0 row, contributing 0.5*yp[col,0]^2
    // regardless of which row got it.
    if (pm[tid] != 3.0f) {
        float p0 = yp_s[tid * F_ + 0];
        term += LAMBDA_NOOBJ * p0 * p0;
    }

    // Block reduction (2 warps), then grid reduction via device scratch.
#pragma unroll
    for (int o = 16; o; o >>= 1) term += __shfl_down_sync(FULLM, term, o);
    if ((tid & 31) == 0) red[tid >> 5] = term;
    __syncthreads();

    if (tid == 0) {
        atomicAdd(&g_acc, red[0] + red[1]);
        __threadfence();
        unsigned ticket = atomicAdd(&g_count, 1u);
        if (ticket == gridDim.x - 1) {                // last block finalizes
            float total = atomicAdd(&g_acc, 0.0f);    // coherent read
            out[0]  = total;
            g_acc   = 0.0f;                           // reset for next replay
            g_count = 0u;
        }
    }
}

extern "C" void kernel_launch(void* const* d_in, const int* in_sizes, int n_in,
                              void* d_out, int out_size)
{
    const float* y_true = (const float*)d_in[0];
    const float* y_pred = (const float*)d_in[1];
    float* out = (float*)d_out;

    int batches = in_sizes[0] / (N_ * F_);   // 2048
    spotting_loss_kernel<<<batches, N_>>>(y_true, y_pred, out);
}

// round 10
// speedup vs baseline: 1.0173x; 1.0173x over previous
#include <cuda_runtime.h>
#include <cstdint>

// SpottingLoss: greedy bipartite matching + YOLO-style loss.
// B=2048 batches, N=64 slots, F=19 features. ONE 32-THREAD WARP PER BATCH.
// R9: fully warp-synchronous matching — no bar.sync anywhere in the loop.
//     Active alpha=1 rows are compacted onto lanes each round (ballot mask +
//     __fns + shuffle of x), so every lane does at most one 64-col scan per
//     round. Acceptance via smem atomicMax keys (proven), winners poison pm
//     and atomicAnd the shared active mask.
// Kept from earlier rounds: phase-1 elimination, pm-poison free-set,
// 8x8 tree argmax, direct-global epilogue (R7), fused grid reduction (R6).

#define N_ 64
#define F_ 19
#define LAMBDA_COORD 5.0f
#define LAMBDA_NOOBJ 0.5f
#define FULLM 0xFFFFFFFFu

// Grid-reduction scratch. Zero-initialized at module load; the LAST block of
// every launch resets both, so each graph replay starts clean.
__device__ float    g_acc   = 0.0f;
__device__ unsigned g_count = 0u;

// Column-acceptance key: (value bits << 32) | ~row. Proposal values are > 0,
// so float bits are monotone; larger key = larger value, then lower row index
// — exactly the reference's argmax-over-rows tie-breaking.
__device__ __forceinline__ unsigned long long mk_key(float v, int row) {
    return ((unsigned long long)__float_as_uint(v) << 32) |
           (unsigned long long)(FULLM - (unsigned)row);
}

__global__ __launch_bounds__(32) void spotting_loss_kernel(
    const float* __restrict__ y_true,
    const float* __restrict__ y_pred,
    float* __restrict__ out)
{
    // pm[j] = y_pred[j][1] while column j is free; poisoned to 3.0f once
    // matched (v = 1-|x-3| < 0 never beats a free column's v > 0).
    // After matching, pm[j]==3.0f doubles as the "column taken" flag.
    __shared__ float pm[N_];
    __shared__ unsigned long long colkey[N_];
    __shared__ int perm_s[N_];
    __shared__ unsigned long long act_s;

    const int lane = threadIdx.x;
    const int b    = blockIdx.x;

    const float* gt = y_true + (size_t)b * (N_ * F_);
    const float* gp = y_pred + (size_t)b * (N_ * F_);

    const int r0 = lane, r1 = lane + 32;

    // Startup: 6 scattered LDGs per lane (2 rows' alpha/x + 2 columns' p).
    const float a0 = __ldg(gt + r0 * F_ + 0);   // exactly 0.0f or 1.0f
    const float x0 = __ldg(gt + r0 * F_ + 1);
    const float a1 = __ldg(gt + r1 * F_ + 0);
    const float x1 = __ldg(gt + r1 * F_ + 1);
    pm[r0] = __ldg(gp + r0 * F_ + 1);
    pm[r1] = __ldg(gp + r1 * F_ + 1);
    colkey[r0] = 0ull;            // init once; never reset (round invariant)
    colkey[r1] = 0ull;

    // Active mask over 64 rows (alpha==1 rows only; phase 1 is eliminated).
    unsigned bl0 = __ballot_sync(FULLM, a0 > 0.5f);
    unsigned bl1 = __ballot_sync(FULLM, a1 > 0.5f);
    unsigned long long act = (unsigned long long)bl0 |
                             ((unsigned long long)bl1 << 32);
    if (lane == 0) act_s = act;
    __syncwarp();

    // Invariant: every column proposed in a round is matched in that round,
    // so colkey entries are never reused and pm poison is the only free-set.
    while (act) {
        const int      cnt = __popcll(act);
        const unsigned lo  = (unsigned)act;
        const unsigned hi  = (unsigned)(act >> 32);
        const int      plo = __popc(lo);

        int pr[2], pj[2];
        pr[0] = pr[1] = -1;

        // Proposal pass: lane takes the (base+lane)-th active row (ascending).
        for (int base = 0; base < cnt; base += 32) {
            const int  t   = base >> 5;
            const int  i   = base + lane;
            const bool has = i < cnt;
            const int  idx = has ? i : 0;
            const int  r   = (idx < plo)
                           ? (int)__fns(lo, 0, idx + 1)
                           : 32 + (int)__fns(hi, 0, idx - plo + 1);
            // Fetch the assigned row's x by shuffle (all lanes participate).
            const float xA = __shfl_sync(FULLM, x0, r & 31);
            const float xB = __shfl_sync(FULLM, x1, r & 31);
            const float xr = (r < 32) ? xA : xB;

            if (has) {
                // Two-level argmax over all 64 columns: 8 independent chunk
                // chains (ILP=8), then serial combine. Strict > keeps the
                // lowest index on ties at both levels = JAX argmax semantics.
                float cv[8]; int cj[8];
#pragma unroll
                for (int c = 0; c < 8; ++c) {
                    float bv = -10.0f; int bi = c * 8;
#pragma unroll
                    for (int k = 0; k < 8; ++k) {
                        int j = c * 8 + k;
                        float v = 1.0f - fabsf(xr - pm[j]);
                        if (v > bv) { bv = v; bi = j; }
                    }
                    cv[c] = bv; cj[c] = bi;
                }
                float bv = cv[0]; int bj = cj[0];
#pragma unroll
                for (int c = 1; c < 8; ++c)
                    if (cv[c] > bv) { bv = cv[c]; bj = cj[c]; }

                atomicMax(&colkey[bj], mk_key(bv, r));
                pr[t] = r; pj[t] = bj;
            }
        }
        __syncwarp();                      // proposals visible warp-wide

        // Acceptance pass: the max-key proposer of each proposed column wins,
        // poisons it, records perm, and retires its row from the active mask.
        for (int base = 0; base < cnt; base += 32) {
            const int t = base >> 5;
            const int r = pr[t];
            if (r >= 0) {
                const int bj = pj[t];
                unsigned wr = FULLM - (unsigned)(colkey[bj] & 0xFFFFFFFFull);
                if (wr == (unsigned)r) {
                    perm_s[r] = bj;
                    pm[bj]    = 3.0f;      // poison (single writer)
                    atomicAnd(&act_s, ~(1ull << r));
                }
            }
        }
        __syncwarp();                      // poison + mask updates visible
        act = act_s;
    }
    // Last loop iteration ended with __syncwarp -> pm/perm_s final here.

    float term = 0.0f;

    // alpha=1 row terms: full YOLO loss vs permuted prediction rows
    // (direct global reads; hidden by other resident CTAs' matching work).
    if (a0 > 0.5f) {
        const float* gtr = gt + r0 * F_;
        const float* ypr = gp + perm_s[r0] * F_;
        const float d0 = 1.0f - __ldg(ypr + 0);
        const float dx = x0 - __ldg(ypr + 1);
        float s = 0.0f;
#pragma unroll
        for (int f = 2; f < F_; ++f) {
            float d = __ldg(gtr + f) - __ldg(ypr + f);
            s += d * d;
        }
        term += LAMBDA_COORD * dx * dx + d0 * d0 + s;
    }
    if (a1 > 0.5f) {
        const float* gtr = gt + r1 * F_;
        const float* ypr = gp + perm_s[r1] * F_;
        const float d0 = 1.0f - __ldg(ypr + 0);
        const float dx = x1 - __ldg(ypr + 1);
        float s = 0.0f;
#pragma unroll
        for (int f = 2; f < F_; ++f) {
            float d = __ldg(gtr + f) - __ldg(ypr + f);
            s += d * d;
        }
        term += LAMBDA_COORD * dx * dx + d0 * d0 + s;
    }

    // alpha=0 contribution, per COLUMN: every column not taken in phase 0 is
    // assigned to exactly one alpha=0 row, contributing 0.5*yp[col,0]^2
    // regardless of which row got it.
    if (pm[r0] != 3.0f) {
        float p = __ldg(gp + r0 * F_ + 0);
        term += LAMBDA_NOOBJ * p * p;
    }
    if (pm[r1] != 3.0f) {
        float p = __ldg(gp + r1 * F_ + 0);
        term += LAMBDA_NOOBJ * p * p;
    }

    // Warp reduction, then grid reduction via device scratch.
#pragma unroll
    for (int o = 16; o; o >>= 1) term += __shfl_down_sync(FULLM, term, o);

    if (lane == 0) {
        atomicAdd(&g_acc, term);
        __threadfence();
        unsigned ticket = atomicAdd(&g_count, 1u);
        if (ticket == gridDim.x - 1) {                // last block finalizes
            float total = atomicAdd(&g_acc, 0.0f);    // coherent read
            out[0]  = total;
            g_acc   = 0.0f;                           // reset for next replay
            g_count = 0u;
        }
    }
}

extern "C" void kernel_launch(void* const* d_in, const int* in_sizes, int n_in,
                              void* d_out, int out_size)
{
    const float* y_true = (const float*)d_in[0];
    const float* y_pred = (const float*)d_in[1];
    float* out = (float*)d_out;

    int batches = in_sizes[0] / (N_ * F_);   // 2048
    spotting_loss_kernel<<<batches, 32>>>(y_true, y_pred, out);
}